// round 11
// baseline (speedup 1.0000x reference)
#include <cuda_runtime.h>
#include <cuda_fp16.h>
#include <math.h>
#include <math_constants.h>

#define SEQ 4096
#define TT  4096
#define CHQ 1024
#define ED  64
#define MF  128
#define NHk 8
#define NG  128
#define LOGM 4.852030263919617f

__device__ __half g_phikh[(size_t)NG*SEQ*MF];
__device__ __half g_phiqh[(size_t)NG*CHQ*MF];
__device__ float  g_tstab[NG*32];
__device__ float  g_pstab[NG*8];
__device__ float  g_stabk[NG];
__device__ float  g_kvp[(size_t)NG*8*MF*ED];
__device__ float  g_kv[NG*MF*ED];
__device__ float  g_ksump[NG*8*MF];
__device__ float  g_ksum[NG*MF];
__device__ float  g_pls[NG*CHQ];
__device__ float  g_lr1[NG*CHQ];
__device__ float  g_lrv[(size_t)NG*CHQ*ED];

__device__ __forceinline__ void mma16816(float* c, unsigned a0,unsigned a1,unsigned a2,unsigned a3,
                                         unsigned b0,unsigned b1){
  asm volatile("mma.sync.aligned.m16n8k16.row.col.f32.f16.f16.f32 "
    "{%0,%1,%2,%3},{%4,%5,%6,%7},{%8,%9},{%0,%1,%2,%3};"
    : "+f"(c[0]),"+f"(c[1]),"+f"(c[2]),"+f"(c[3])
    : "r"(a0),"r"(a1),"r"(a2),"r"(a3),"r"(b0),"r"(b1));
}
__device__ __forceinline__ void ldsm4(unsigned&r0,unsigned&r1,unsigned&r2,unsigned&r3,const __half*p){
  unsigned a=(unsigned)__cvta_generic_to_shared(p);
  asm volatile("ldmatrix.sync.aligned.m8n8.x4.shared.b16 {%0,%1,%2,%3}, [%4];"
    :"=r"(r0),"=r"(r1),"=r"(r2),"=r"(r3):"r"(a));
}
__device__ __forceinline__ void ldsm4t(unsigned&r0,unsigned&r1,unsigned&r2,unsigned&r3,const __half*p){
  unsigned a=(unsigned)__cvta_generic_to_shared(p);
  asm volatile("ldmatrix.sync.aligned.m8n8.x4.trans.shared.b16 {%0,%1,%2,%3}, [%4];"
    :"=r"(r0),"=r"(r1),"=r"(r2),"=r"(r3):"r"(a));
}
__device__ __forceinline__ void split16(float x, __half& h, __half& l){
  h = __float2half_rn(x); l = __float2half_rn(x - __half2float(h));
}

__constant__ int c_ao[3] = {0, 64, 0};
__constant__ int c_bo[3] = {0, 0, 64};

// ======== K1: logk mma + phi_k + kv mma (ldmatrix, register acc) ========
struct SP {
  __half Bp[128][136];
  union { __half Ak[128][136]; __half phiS[128][136]; } u;   // phiS row-major [s][m]
  __half vT[64][136];
  float snorm[128];
  float wred[8];
  float ks2[256];
};

__global__ void __launch_bounds__(256,2)
k_phik(const float* __restrict__ key, const float* __restrict__ value,
       const float* __restrict__ proj){
  extern __shared__ char raw[];
  SP& sm = *reinterpret_cast<SP*>(raw);
  int g = blockIdx.y, split = blockIdx.x;
  int c = g>>5, b = (g>>3)&3, h = g&7;
  int tid = threadIdx.x, lane = tid&31, w = tid>>5;
  int gg = lane>>2, t = lane&3;
  int arow = (lane&7) + ((lane>>3)&1)*8, acol = (lane>>4)*8;
  int trow = (lane&7) + (lane>>4)*8,     tcol = ((lane>>3)&1)*8;

  for (int idx = tid; idx < 128*64; idx += 256){
    int m = idx>>6, e = idx&63;
    float x = proj[((size_t)c*MF+m)*ED+e];
    __half hh,ll; split16(x,hh,ll);
    sm.Bp[m][e]=hh; sm.Bp[m][64+e]=ll;
  }

  float kvacc[8][4];
  #pragma unroll
  for(int i=0;i<8;i++)
    #pragma unroll
    for(int j=0;j<4;j++) kvacc[i][j]=0.f;
  float kpriv = 0.f;
  float runstab = -CUDART_INF_F;

  for (int tile = 0; tile < 4; tile++){
    int sbase = split*512 + tile*128;
    __syncthreads();
    for (int idx = tid; idx < 128*64; idx += 256){
      int s = idx>>6, e = idx&63;
      size_t gb = (((size_t)b*SEQ + sbase + s)*NHk + h)*ED + e;
      float x = key[gb];
      __half hh,ll; split16(x,hh,ll);
      sm.u.Ak[s][e]=hh; sm.u.Ak[s][64+e]=ll;
      sm.vT[e][s] = __float2half_rn(value[gb]);
    }
    __syncthreads();
    if (tid < 128){
      float s = 0.f;
      #pragma unroll
      for (int e = 0; e < 64; e++){
        float x = __half2float(sm.u.Ak[tid][e]) + __half2float(sm.u.Ak[tid][64+e]);
        s += x*x;
      }
      sm.snorm[tid] = 0.5f*s;
    }
    __syncthreads();

    int r0 = w*16+gg, r1 = r0+8;
    float fr[16][4];
    #pragma unroll
    for(int i=0;i<16;i++)
      #pragma unroll
      for(int j=0;j<4;j++) fr[i][j]=0.f;
    #pragma unroll
    for (int term = 0; term < 3; term++){
      int ao = c_ao[term], bo = c_bo[term];
      #pragma unroll
      for (int ks = 0; ks < 4; ks++){
        int k0 = ks*16;
        unsigned a0,a1,a2,a3;
        ldsm4(a0,a1,a2,a3, &sm.u.Ak[w*16 + arow][ao + k0 + acol]);
        #pragma unroll
        for (int p = 0; p < 8; p++){
          unsigned b0,b1,b2,b3;
          ldsm4(b0,b1,b2,b3, &sm.Bp[p*16 + arow][bo + k0 + acol]);
          mma16816(fr[2*p],   a0,a1,a2,a3, b0,b2);
          mma16816(fr[2*p+1], a0,a1,a2,a3, b1,b3);
        }
      }
    }
    float n0v = sm.snorm[r0], n1v = sm.snorm[r1];
    float mx = -CUDART_INF_F;
    #pragma unroll
    for(int ft=0;ft<16;ft++){
      fr[ft][0]-=n0v; fr[ft][1]-=n0v; fr[ft][2]-=n1v; fr[ft][3]-=n1v;
      mx = fmaxf(mx, fmaxf(fmaxf(fr[ft][0],fr[ft][1]),fmaxf(fr[ft][2],fr[ft][3])));
    }
    #pragma unroll
    for (int o=16;o>0;o>>=1) mx = fmaxf(mx, __shfl_xor_sync(0xffffffffu,mx,o));
    if (lane==0) sm.wred[w] = mx;
    __syncthreads();
    float tstab = sm.wred[0];
    #pragma unroll
    for (int q=1;q<8;q++) tstab = fmaxf(tstab, sm.wred[q]);
    if (tid==0) g_tstab[g*32 + split*4 + tile] = tstab;
    float newstab = fmaxf(runstab, tstab);
    float fo = __expf(runstab - newstab);
    float fn = __expf(tstab - newstab);
    runstab = newstab;

    size_t gr0 = ((size_t)g*SEQ + sbase + r0)*MF;
    size_t gr1 = ((size_t)g*SEQ + sbase + r1)*MF;
    #pragma unroll
    for(int ft=0;ft<16;ft++){
      int col = ft*8 + 2*t;
      __half h0 = __float2half_rn(__expf(fr[ft][0]-tstab));
      __half h1 = __float2half_rn(__expf(fr[ft][1]-tstab));
      __half h2 = __float2half_rn(__expf(fr[ft][2]-tstab));
      __half h3 = __float2half_rn(__expf(fr[ft][3]-tstab));
      __half2 p01 = __halves2half2(h0,h1), p23 = __halves2half2(h2,h3);
      *(__half2*)&g_phikh[gr0+col] = p01;
      *(__half2*)&g_phikh[gr1+col] = p23;
      *(__half2*)&sm.u.phiS[r0][col] = p01;
      *(__half2*)&sm.u.phiS[r1][col] = p23;
    }
    __syncthreads();

    if (tid < 128){
      float s = 0.f;
      #pragma unroll
      for (int s_ = 0; s_ < 128; s_++) s += __half2float(sm.u.phiS[s_][tid]);
      kpriv = kpriv*fo + fn*s;
    }

    float tmp[8][4];
    #pragma unroll
    for(int i=0;i<8;i++)
      #pragma unroll
      for(int j=0;j<4;j++) tmp[i][j]=0.f;
    #pragma unroll
    for (int ks = 0; ks < 8; ks++){
      int k0 = ks*16;
      unsigned a0,a1,a2,a3;
      ldsm4t(a0,a1,a2,a3, &sm.u.phiS[k0 + trow][w*16 + tcol]);
      #pragma unroll
      for (int p = 0; p < 4; p++){
        unsigned b0,b1,b2,b3;
        ldsm4(b0,b1,b2,b3, &sm.vT[p*16 + arow][k0 + acol]);
        mma16816(tmp[2*p],   a0,a1,a2,a3, b0,b2);
        mma16816(tmp[2*p+1], a0,a1,a2,a3, b1,b3);
      }
    }
    #pragma unroll
    for(int i=0;i<8;i++)
      #pragma unroll
      for(int j=0;j<4;j++) kvacc[i][j] = kvacc[i][j]*fo + tmp[i][j]*fn;
  }

  size_t pb = ((size_t)g*8 + split)*(MF*ED);
  int m0 = w*16+gg, m1 = m0+8;
  #pragma unroll
  for (int nt = 0; nt < 8; nt++){
    int e0 = nt*8 + 2*t;
    *(float2*)&g_kvp[pb + (size_t)m0*64 + e0] = make_float2(kvacc[nt][0], kvacc[nt][1]);
    *(float2*)&g_kvp[pb + (size_t)m1*64 + e0] = make_float2(kvacc[nt][2], kvacc[nt][3]);
  }
  sm.ks2[tid] = kpriv;
  __syncthreads();
  if (tid < 128) g_ksump[((size_t)g*8 + split)*MF + tid] = sm.ks2[tid];
  if (tid == 0) g_pstab[g*8 + split] = runstab;
}

// ======== K2: stab ; K3: merged kv+ksum reduction ========
__global__ void k_stab(){
  int g = blockIdx.x, lane = threadIdx.x;
  float v = g_tstab[g*32 + lane];
  #pragma unroll
  for (int o=16;o>0;o>>=1) v = fmaxf(v, __shfl_xor_sync(0xffffffffu,v,o));
  if (lane==0) g_stabk[g] = v;
}
__global__ void k_red(){
  int i = blockIdx.x*blockDim.x + threadIdx.x;
  if (i < NG*MF*ED){
    int g = i>>13, me = i&8191;
    float stabg = g_stabk[g], s = 0.f;
    #pragma unroll
    for (int p=0;p<8;p++)
      s += g_kvp[((size_t)g*8+p)*(MF*ED)+me] * __expf(g_pstab[g*8+p]-stabg);
    g_kv[i] = s;
  } else {
    int j = i - NG*MF*ED;
    if (j < NG*MF){
      int g = j>>7, m = j&127;
      float stabg = g_stabk[g], s = 0.f;
      #pragma unroll
      for (int p=0;p<8;p++)
        s += g_ksump[(size_t)(g*8+p)*MF+m] * __expf(g_pstab[g*8+p]-stabg);
      g_ksum[j] = s;
    }
  }
}

// ======== K4: phi_q (mma), pls, lr_v (mma), lr_1 ========
struct SQ {
  __half Bp[128][136];
  union { __half Aq[128][136]; __half phiA[128][136]; } u;   // phiA row-major [q][m]
  __half kvTh[64][136];
  __half kvTl[64][136];
  float snorm[128];
  float ksum[128];
};

__global__ void __launch_bounds__(256,2)
k_phiq(const float* __restrict__ query, const float* __restrict__ proj){
  extern __shared__ char raw[];
  SQ& sm = *reinterpret_cast<SQ*>(raw);
  int g = blockIdx.y;
  int c = g>>5, b = (g>>3)&3, h = g&7;
  int q0 = blockIdx.x*128;
  int tid = threadIdx.x, lane = tid&31, w = tid>>5;
  int gg = lane>>2, t = lane&3;
  int arow = (lane&7) + ((lane>>3)&1)*8, acol = (lane>>4)*8;

  for (int idx = tid; idx < 128*64; idx += 256){
    int m = idx>>6, e = idx&63;
    float x = proj[((size_t)c*MF+m)*ED+e];
    __half hh,ll; split16(x,hh,ll);
    sm.Bp[m][e]=hh; sm.Bp[m][64+e]=ll;
  }
  for (int idx = tid; idx < 128*64; idx += 256){
    int i = idx>>6, e = idx&63;
    float x = query[(((size_t)b*TT + (c*CHQ+q0+i))*NHk + h)*ED + e];
    __half hh,ll; split16(x,hh,ll);
    sm.u.Aq[i][e]=hh; sm.u.Aq[i][64+e]=ll;
  }
  for (int idx = tid; idx < 128*64; idx += 256){
    int m = idx>>6, e = idx&63;
    float x = g_kv[(size_t)g*MF*ED + m*64 + e];
    __half hh,ll; split16(x,hh,ll);
    sm.kvTh[e][m]=hh; sm.kvTl[e][m]=ll;
  }
  if (tid < 128) sm.ksum[tid] = g_ksum[g*MF+tid];
  __syncthreads();
  if (tid < 128){
    float s = 0.f;
    #pragma unroll
    for (int e = 0; e < 64; e++){
      float x = __half2float(sm.u.Aq[tid][e]) + __half2float(sm.u.Aq[tid][64+e]);
      s += x*x;
    }
    sm.snorm[tid] = 0.5f*s;
  }
  __syncthreads();

  int r0 = w*16+gg, r1 = r0+8;
  float fr[16][4];
  #pragma unroll
  for(int i=0;i<16;i++)
    #pragma unroll
    for(int j=0;j<4;j++) fr[i][j]=0.f;
  #pragma unroll
  for (int term = 0; term < 3; term++){
    int ao = c_ao[term], bo = c_bo[term];
    #pragma unroll
    for (int ks = 0; ks < 4; ks++){
      int k0 = ks*16;
      unsigned a0,a1,a2,a3;
      ldsm4(a0,a1,a2,a3, &sm.u.Aq[w*16 + arow][ao + k0 + acol]);
      #pragma unroll
      for (int p = 0; p < 8; p++){
        unsigned b0,b1,b2,b3;
        ldsm4(b0,b1,b2,b3, &sm.Bp[p*16 + arow][bo + k0 + acol]);
        mma16816(fr[2*p],   a0,a1,a2,a3, b0,b2);
        mma16816(fr[2*p+1], a0,a1,a2,a3, b1,b3);
      }
    }
  }
  float n0v = sm.snorm[r0], n1v = sm.snorm[r1];
  float m0 = -CUDART_INF_F, m1 = -CUDART_INF_F;
  #pragma unroll
  for(int ft=0;ft<16;ft++){
    fr[ft][0]-=n0v; fr[ft][1]-=n0v; fr[ft][2]-=n1v; fr[ft][3]-=n1v;
    m0 = fmaxf(m0, fmaxf(fr[ft][0], fr[ft][1]));
    m1 = fmaxf(m1, fmaxf(fr[ft][2], fr[ft][3]));
  }
  #pragma unroll
  for (int o=1;o<=2;o<<=1){
    m0 = fmaxf(m0, __shfl_xor_sync(0xffffffffu,m0,o));
    m1 = fmaxf(m1, __shfl_xor_sync(0xffffffffu,m1,o));
  }
  float skv = g_stabk[g];
  if (t == 0){
    g_pls[(size_t)g*CHQ + q0 + r0] = m0 + skv - LOGM;
    g_pls[(size_t)g*CHQ + q0 + r1] = m1 + skv - LOGM;
  }
  __syncthreads();
  size_t gq0 = ((size_t)g*CHQ+q0+r0)*MF;
  size_t gq1 = ((size_t)g*CHQ+q0+r1)*MF;
  #pragma unroll
  for(int ft=0;ft<16;ft++){
    int col = ft*8 + 2*t;
    __half h0 = __float2half_rn(__expf(fr[ft][0]-m0));
    __half h1 = __float2half_rn(__expf(fr[ft][1]-m0));
    __half h2 = __float2half_rn(__expf(fr[ft][2]-m1));
    __half h3 = __float2half_rn(__expf(fr[ft][3]-m1));
    __half2 p01 = __halves2half2(h0,h1), p23 = __halves2half2(h2,h3);
    *(__half2*)&sm.u.phiA[r0][col] = p01;
    *(__half2*)&sm.u.phiA[r1][col] = p23;
    *(__half2*)&g_phiqh[gq0+col] = p01;
    *(__half2*)&g_phiqh[gq1+col] = p23;
  }
  __syncthreads();

  float acc[8][4];
  #pragma unroll
  for(int i=0;i<8;i++)
    #pragma unroll
    for(int j=0;j<4;j++) acc[i][j]=0.f;
  #pragma unroll
  for (int pass=0; pass<2; pass++){
    #pragma unroll
    for (int ks = 0; ks < 8; ks++){
      int k0 = ks*16;
      unsigned a0,a1,a2,a3;
      ldsm4(a0,a1,a2,a3, &sm.u.phiA[w*16 + arow][k0 + acol]);
      #pragma unroll
      for (int p = 0; p < 4; p++){
        const __half* br = pass ? &sm.kvTl[p*16 + arow][k0 + acol]
                                : &sm.kvTh[p*16 + arow][k0 + acol];
        unsigned b0,b1,b2,b3;
        ldsm4(b0,b1,b2,b3, br);
        mma16816(acc[2*p],   a0,a1,a2,a3, b0,b2);
        mma16816(acc[2*p+1], a0,a1,a2,a3, b1,b3);
      }
    }
  }
  size_t ro0 = ((size_t)g*CHQ + q0 + r0)*ED;
  size_t ro1 = ((size_t)g*CHQ + q0 + r1)*ED;
  #pragma unroll
  for (int nt = 0; nt < 8; nt++){
    int e0 = nt*8 + 2*t;
    *(float2*)&g_lrv[ro0 + e0] = make_float2(acc[nt][0], acc[nt][1]);
    *(float2*)&g_lrv[ro1 + e0] = make_float2(acc[nt][2], acc[nt][3]);
  }
  if (tid < 128){
    const __half2* p2 = (const __half2*)&sm.u.phiA[tid][0];
    float s = 0.f;
    #pragma unroll
    for (int i = 0; i < 64; i++){
      float2 f = __half22float2(p2[i]);
      s += f.x*sm.ksum[2*i] + f.y*sm.ksum[2*i+1];
    }
    g_lr1[(size_t)g*CHQ + q0 + tid] = s;
  }
}

// ======== K5: local windows via mma (ldmatrix) ========
struct S5 {
  union { __half A_s[32][200]; __half cA[32][200]; } u;
  __half B_s[64][200];
  __half vT[64][200];
  __half pqA[32][136];
  __half pkB[64][136];
  float sc[32][66];
  float dp[32][66];
  float jscale[64];
  float lnorm[32];
  float scl[32];
};

__global__ void __launch_bounds__(256,2)
k_local(const float* __restrict__ query, const float* __restrict__ key,
        const float* __restrict__ value, float* __restrict__ out){
  extern __shared__ char raw[];
  S5& sm = *reinterpret_cast<S5*>(raw);
  int g = blockIdx.y, n = blockIdx.x;
  int c = g>>5, b = (g>>3)&3, h = g&7;
  int tid = threadIdx.x, lane = tid&31, w = tid>>5;
  int t = lane&3;
  int arow = (lane&7) + ((lane>>3)&1)*8, acol = (lane>>4)*8;
  int t0 = n*32, p0 = t0 - 16;
  float stabg = g_stabk[g];

  if (tid < 64){
    int pos = p0 + tid;
    sm.jscale[tid] = (pos >= 0) ? __expf(g_tstab[g*32 + (pos>>7)] - stabg) : 0.f;
  }
  for (int idx = tid; idx < 32*64; idx += 256){
    int qi = idx>>6, e = idx&63;
    float x = query[(((size_t)b*TT + (c*CHQ+t0+qi))*NHk + h)*ED + e];
    __half hh,ll; split16(x,hh,ll);
    sm.u.A_s[qi][e]=hh; sm.u.A_s[qi][64+e]=ll; sm.u.A_s[qi][128+e]=hh;
  }
  for (int idx = tid; idx < 64*64; idx += 256){
    int j = idx>>6, e = idx&63;
    int pos = p0 + j;
    float kx = 0.f, vx = 0.f;
    if (pos >= 0){
      size_t base = (((size_t)b*SEQ + pos)*NHk + h)*ED + e;
      kx = key[base]; vx = value[base];
    }
    __half hh,ll; split16(kx,hh,ll);
    sm.B_s[j][e]=hh; sm.B_s[j][64+e]=hh; sm.B_s[j][128+e]=ll;
    __half vh,vl; split16(vx,vh,vl);
    sm.vT[e][j]=vh; sm.vT[e][64+j]=vl; sm.vT[e][128+j]=vh;
  }
  for (int idx = tid; idx < 32*64; idx += 256){
    int qi = idx>>6, mp = idx&63;
    *(unsigned*)&sm.pqA[qi][2*mp] =
      *(const unsigned*)&g_phiqh[((size_t)g*CHQ + t0 + qi)*MF + 2*mp];
  }
  for (int idx = tid; idx < 64*64; idx += 256){
    int j = idx>>6, mp = idx&63;
    int pos = p0 + j;
    unsigned v = 0u;
    if (pos >= 0) v = *(const unsigned*)&g_phikh[((size_t)g*SEQ + pos)*MF + 2*mp];
    *(unsigned*)&sm.pkB[j][2*mp] = v;
  }
  __syncthreads();

  int mt = w&1, ntb = (w>>1)*2;
  int row0 = mt*16 + (lane>>2), row1 = row0+8;

  float cs[2][4], cd[2][4];
  #pragma unroll
  for(int i=0;i<2;i++)
    #pragma unroll
    for(int j=0;j<4;j++){ cs[i][j]=0.f; cd[i][j]=0.f; }
  #pragma unroll
  for (int ks = 0; ks < 12; ks++){
    int k0 = ks*16;
    unsigned a0,a1,a2,a3, b0,b1,b2,b3;
    ldsm4(a0,a1,a2,a3, &sm.u.A_s[mt*16 + arow][k0 + acol]);
    ldsm4(b0,b1,b2,b3, &sm.B_s[(w>>1)*16 + arow][k0 + acol]);
    mma16816(cs[0], a0,a1,a2,a3, b0,b2);
    mma16816(cs[1], a0,a1,a2,a3, b1,b3);
  }
  #pragma unroll
  for (int ks = 0; ks < 8; ks++){
    int k0 = ks*16;
    unsigned a0,a1,a2,a3, b0,b1,b2,b3;
    ldsm4(a0,a1,a2,a3, &sm.pqA[mt*16 + arow][k0 + acol]);
    ldsm4(b0,b1,b2,b3, &sm.pkB[(w>>1)*16 + arow][k0 + acol]);
    mma16816(cd[0], a0,a1,a2,a3, b0,b2);
    mma16816(cd[1], a0,a1,a2,a3, b1,b3);
  }
  #pragma unroll
  for (int ii = 0; ii < 2; ii++){
    int colb = (ntb+ii)*8 + 2*t;
    #pragma unroll
    for (int cc = 0; cc < 2; cc++){
      int j = colb + cc;
      float js = sm.jscale[j];
      bool ok = (p0 + j >= 0);
      bool v0 = ok && (j>=row0) && (j<row0+32);
      bool v1 = ok && (j>=row1) && (j<row1+32);
      cs[ii][cc]   = v0 ? cs[ii][cc]      : -1e24f;
      cs[ii][2+cc] = v1 ? cs[ii][2+cc]    : -1e24f;
      cd[ii][cc]   = v0 ? cd[ii][cc]*js   : 0.f;
      cd[ii][2+cc] = v1 ? cd[ii][2+cc]*js : 0.f;
      sm.sc[row0][j] = cs[ii][cc];
      sm.sc[row1][j] = cs[ii][2+cc];
      sm.dp[row0][j] = cd[ii][cc];
      sm.dp[row1][j] = cd[ii][2+cc];
    }
  }
  __syncthreads();

  #pragma unroll
  for(int r=0;r<4;r++){
    int row = w*4+r;
    float v0 = sm.sc[row][lane], v1 = sm.sc[row][lane+32];
    float mx = fmaxf(v0,v1);
    #pragma unroll
    for(int o=16;o>0;o>>=1) mx = fmaxf(mx, __shfl_xor_sync(0xffffffffu,mx,o));
    float se = __expf(v0-mx) + __expf(v1-mx);
    #pragma unroll
    for(int o=16;o>0;o>>=1) se += __shfl_xor_sync(0xffffffffu,se,o);
    float lse = mx + __logf(se);
    float ds = sm.dp[row][lane] + sm.dp[row][lane+32];
    #pragma unroll
    for(int o=16;o>0;o>>=1) ds += __shfl_xor_sync(0xffffffffu,ds,o);
    float lr1v = g_lr1[(size_t)g*CHQ + t0 + row];
    float plsv = g_pls[(size_t)g*CHQ + t0 + row];
    float rem = fmaxf(lr1v - ds, 1e-24f);
    float bq = __logf(rem) + plsv;
    float hi = fmaxf(lse,bq), lo2 = fminf(lse,bq);
    float ln = hi + __logf(1.f + __expf(lo2-hi));
    if (lane==0){ sm.lnorm[row]=ln; sm.scl[row]=__expf(plsv-ln); }
  }
  __syncthreads();

  float ln0 = sm.lnorm[row0], ln1 = sm.lnorm[row1];
  float s0v = sm.scl[row0], s1v = sm.scl[row1];
  #pragma unroll
  for (int ii = 0; ii < 2; ii++){
    int colb = (ntb+ii)*8 + 2*t;
    #pragma unroll
    for (int cc = 0; cc < 2; cc++){
      int j = colb + cc;
      float c0 = __expf(cs[ii][cc]   - ln0) - s0v*cd[ii][cc];
      float c1 = __expf(cs[ii][2+cc] - ln1) - s1v*cd[ii][2+cc];
      __half ch, cl;
      split16(c0, ch, cl);
      sm.u.cA[row0][j]=ch; sm.u.cA[row0][64+j]=ch; sm.u.cA[row0][128+j]=cl;
      split16(c1, ch, cl);
      sm.u.cA[row1][j]=ch; sm.u.cA[row1][64+j]=ch; sm.u.cA[row1][128+j]=cl;
    }
  }
  __syncthreads();

  float ep[2][4];
  #pragma unroll
  for(int i=0;i<2;i++)
    #pragma unroll
    for(int j=0;j<4;j++) ep[i][j]=0.f;
  #pragma unroll
  for (int ks = 0; ks < 12; ks++){
    int k0 = ks*16;
    unsigned a0,a1,a2,a3, b0,b1,b2,b3;
    ldsm4(a0,a1,a2,a3, &sm.u.cA[mt*16 + arow][k0 + acol]);
    ldsm4(b0,b1,b2,b3, &sm.vT[(w>>1)*16 + arow][k0 + acol]);
    mma16816(ep[0], a0,a1,a2,a3, b0,b2);
    mma16816(ep[1], a0,a1,a2,a3, b1,b3);
  }
  float sc0 = sm.scl[row0], sc1 = sm.scl[row1];
  size_t lr0 = ((size_t)g*CHQ + t0 + row0)*ED;
  size_t lr1o = ((size_t)g*CHQ + t0 + row1)*ED;
  size_t ob0 = (((size_t)b*NHk + h)*TT + (c*CHQ + t0 + row0))*ED;
  size_t ob1 = (((size_t)b*NHk + h)*TT + (c*CHQ + t0 + row1))*ED;
  #pragma unroll
  for (int ii = 0; ii < 2; ii++){
    int e0 = (ntb+ii)*8 + 2*t;
    float2 l0 = *(const float2*)&g_lrv[lr0 + e0];
    float2 l1 = *(const float2*)&g_lrv[lr1o + e0];
    out[ob0 + e0]   = ep[ii][0] + sc0*l0.x;
    out[ob0 + e0+1] = ep[ii][1] + sc0*l0.y;
    out[ob1 + e0]   = ep[ii][2] + sc1*l1.x;
    out[ob1 + e0+1] = ep[ii][3] + sc1*l1.y;
  }
}

// ---------------- launch ----------------
extern "C" void kernel_launch(void* const* d_in, const int* in_sizes, int n_in,
                              void* d_out, int out_size){
  const float* query = (const float*)d_in[0];
  const float* key   = (const float*)d_in[1];
  const float* value = (const float*)d_in[2];
  const float* proj  = (const float*)d_in[3];
  float* out = (float*)d_out;

  cudaFuncSetAttribute(k_phik, cudaFuncAttributeMaxDynamicSharedMemorySize, (int)sizeof(SP));
  cudaFuncSetAttribute(k_phiq, cudaFuncAttributeMaxDynamicSharedMemorySize, (int)sizeof(SQ));
  cudaFuncSetAttribute(k_local,cudaFuncAttributeMaxDynamicSharedMemorySize, (int)sizeof(S5));

  dim3 gp(8, NG);
  k_phik<<<gp, 256, sizeof(SP)>>>(key, value, proj);
  k_stab<<<NG, 32>>>();
  k_red<<<(NG*MF*ED + NG*MF + 255)/256, 256>>>();
  dim3 gq(CHQ/128, NG);
  k_phiq<<<gq, 256, sizeof(SQ)>>>(query, proj);
  dim3 g5(32, NG);
  k_local<<<g5, 256, sizeof(S5)>>>(query, key, value, out);
}

// round 12
// speedup vs baseline: 1.0187x; 1.0187x over previous
#include <cuda_runtime.h>
#include <cuda_fp16.h>
#include <math.h>
#include <math_constants.h>

#define SEQ 4096
#define TT  4096
#define CHQ 1024
#define ED  64
#define MF  128
#define NHk 8
#define NG  128
#define LOGM 4.852030263919617f

__device__ __half g_phikh[(size_t)NG*SEQ*MF];
__device__ __half g_phiqh[(size_t)NG*CHQ*MF];
__device__ float  g_tstab[NG*32];
__device__ float  g_pstab[NG*8];
__device__ float  g_stabk[NG];
__device__ float  g_kvp[(size_t)NG*8*MF*ED];
__device__ float  g_kv[NG*MF*ED];
__device__ float  g_ksump[NG*8*MF];
__device__ float  g_ksum[NG*MF];
__device__ float  g_pls[NG*CHQ];
__device__ float  g_lr1[NG*CHQ];
__device__ float  g_lrv[(size_t)NG*CHQ*ED];

__device__ __forceinline__ void mma16816(float* c, unsigned a0,unsigned a1,unsigned a2,unsigned a3,
                                         unsigned b0,unsigned b1){
  asm volatile("mma.sync.aligned.m16n8k16.row.col.f32.f16.f16.f32 "
    "{%0,%1,%2,%3},{%4,%5,%6,%7},{%8,%9},{%0,%1,%2,%3};"
    : "+f"(c[0]),"+f"(c[1]),"+f"(c[2]),"+f"(c[3])
    : "r"(a0),"r"(a1),"r"(a2),"r"(a3),"r"(b0),"r"(b1));
}
__device__ __forceinline__ void ldsm4(unsigned&r0,unsigned&r1,unsigned&r2,unsigned&r3,const __half*p){
  unsigned a=(unsigned)__cvta_generic_to_shared(p);
  asm volatile("ldmatrix.sync.aligned.m8n8.x4.shared.b16 {%0,%1,%2,%3}, [%4];"
    :"=r"(r0),"=r"(r1),"=r"(r2),"=r"(r3):"r"(a));
}
__device__ __forceinline__ void ldsm4t(unsigned&r0,unsigned&r1,unsigned&r2,unsigned&r3,const __half*p){
  unsigned a=(unsigned)__cvta_generic_to_shared(p);
  asm volatile("ldmatrix.sync.aligned.m8n8.x4.trans.shared.b16 {%0,%1,%2,%3}, [%4];"
    :"=r"(r0),"=r"(r1),"=r"(r2),"=r"(r3):"r"(a));
}
__device__ __forceinline__ void split16(float x, __half& h, __half& l){
  h = __float2half_rn(x); l = __float2half_rn(x - __half2float(h));
}

__constant__ int c_ao[3] = {0, 64, 0};
__constant__ int c_bo[3] = {0, 0, 64};

// ======== K1: logk mma + phi_k + kv mma (ldmatrix, register acc) ========
struct SP {
  __half Bp[128][136];
  union { __half Ak[128][136]; __half phiS[128][136]; } u;   // phiS row-major [s][m]
  __half vT[64][136];
  float snorm[128];
  float wred[8];
  float ks2[256];
};

__global__ void __launch_bounds__(256,2)
k_phik(const float* __restrict__ key, const float* __restrict__ value,
       const float* __restrict__ proj){
  extern __shared__ char raw[];
  SP& sm = *reinterpret_cast<SP*>(raw);
  int g = blockIdx.y, split = blockIdx.x;
  int c = g>>5, b = (g>>3)&3, h = g&7;
  int tid = threadIdx.x, lane = tid&31, w = tid>>5;
  int gg = lane>>2, t = lane&3;
  int arow = (lane&7) + ((lane>>3)&1)*8, acol = (lane>>4)*8;
  int trow = (lane&7) + (lane>>4)*8,     tcol = ((lane>>3)&1)*8;

  for (int idx = tid; idx < 128*64; idx += 256){
    int m = idx>>6, e = idx&63;
    float x = proj[((size_t)c*MF+m)*ED+e];
    __half hh,ll; split16(x,hh,ll);
    sm.Bp[m][e]=hh; sm.Bp[m][64+e]=ll;
  }

  float kvacc[8][4];
  #pragma unroll
  for(int i=0;i<8;i++)
    #pragma unroll
    for(int j=0;j<4;j++) kvacc[i][j]=0.f;
  float kpriv = 0.f;
  float runstab = -CUDART_INF_F;

  for (int tile = 0; tile < 4; tile++){
    int sbase = split*512 + tile*128;
    __syncthreads();
    for (int idx = tid; idx < 128*64; idx += 256){
      int s = idx>>6, e = idx&63;
      size_t gb = (((size_t)b*SEQ + sbase + s)*NHk + h)*ED + e;
      float x = key[gb];
      __half hh,ll; split16(x,hh,ll);
      sm.u.Ak[s][e]=hh; sm.u.Ak[s][64+e]=ll;
      sm.vT[e][s] = __float2half_rn(value[gb]);
    }
    __syncthreads();
    if (tid < 128){
      float s = 0.f;
      #pragma unroll
      for (int e = 0; e < 64; e++){
        float x = __half2float(sm.u.Ak[tid][e]) + __half2float(sm.u.Ak[tid][64+e]);
        s += x*x;
      }
      sm.snorm[tid] = 0.5f*s;
    }
    __syncthreads();

    int r0 = w*16+gg, r1 = r0+8;
    float fr[16][4];
    #pragma unroll
    for(int i=0;i<16;i++)
      #pragma unroll
      for(int j=0;j<4;j++) fr[i][j]=0.f;
    #pragma unroll
    for (int term = 0; term < 3; term++){
      int ao = c_ao[term], bo = c_bo[term];
      #pragma unroll
      for (int ks = 0; ks < 4; ks++){
        int k0 = ks*16;
        unsigned a0,a1,a2,a3;
        ldsm4(a0,a1,a2,a3, &sm.u.Ak[w*16 + arow][ao + k0 + acol]);
        #pragma unroll
        for (int p = 0; p < 8; p++){
          unsigned b0,b1,b2,b3;
          ldsm4(b0,b1,b2,b3, &sm.Bp[p*16 + arow][bo + k0 + acol]);
          mma16816(fr[2*p],   a0,a1,a2,a3, b0,b2);
          mma16816(fr[2*p+1], a0,a1,a2,a3, b1,b3);
        }
      }
    }
    float n0v = sm.snorm[r0], n1v = sm.snorm[r1];
    float mx = -CUDART_INF_F;
    #pragma unroll
    for(int ft=0;ft<16;ft++){
      fr[ft][0]-=n0v; fr[ft][1]-=n0v; fr[ft][2]-=n1v; fr[ft][3]-=n1v;
      mx = fmaxf(mx, fmaxf(fmaxf(fr[ft][0],fr[ft][1]),fmaxf(fr[ft][2],fr[ft][3])));
    }
    #pragma unroll
    for (int o=16;o>0;o>>=1) mx = fmaxf(mx, __shfl_xor_sync(0xffffffffu,mx,o));
    if (lane==0) sm.wred[w] = mx;
    __syncthreads();
    float tstab = sm.wred[0];
    #pragma unroll
    for (int q=1;q<8;q++) tstab = fmaxf(tstab, sm.wred[q]);
    if (tid==0) g_tstab[g*32 + split*4 + tile] = tstab;
    float newstab = fmaxf(runstab, tstab);
    float fo = __expf(runstab - newstab);
    float fn = __expf(tstab - newstab);
    runstab = newstab;

    size_t gr0 = ((size_t)g*SEQ + sbase + r0)*MF;
    size_t gr1 = ((size_t)g*SEQ + sbase + r1)*MF;
    #pragma unroll
    for(int ft=0;ft<16;ft++){
      int col = ft*8 + 2*t;
      __half h0 = __float2half_rn(__expf(fr[ft][0]-tstab));
      __half h1 = __float2half_rn(__expf(fr[ft][1]-tstab));
      __half h2 = __float2half_rn(__expf(fr[ft][2]-tstab));
      __half h3 = __float2half_rn(__expf(fr[ft][3]-tstab));
      __half2 p01 = __halves2half2(h0,h1), p23 = __halves2half2(h2,h3);
      *(__half2*)&g_phikh[gr0+col] = p01;
      *(__half2*)&g_phikh[gr1+col] = p23;
      *(__half2*)&sm.u.phiS[r0][col] = p01;
      *(__half2*)&sm.u.phiS[r1][col] = p23;
    }
    __syncthreads();

    if (tid < 128){
      float s = 0.f;
      #pragma unroll
      for (int s_ = 0; s_ < 128; s_++) s += __half2float(sm.u.phiS[s_][tid]);
      kpriv = kpriv*fo + fn*s;
    }

    float tmp[8][4];
    #pragma unroll
    for(int i=0;i<8;i++)
      #pragma unroll
      for(int j=0;j<4;j++) tmp[i][j]=0.f;
    #pragma unroll
    for (int ks = 0; ks < 8; ks++){
      int k0 = ks*16;
      unsigned a0,a1,a2,a3;
      ldsm4t(a0,a1,a2,a3, &sm.u.phiS[k0 + trow][w*16 + tcol]);
      #pragma unroll
      for (int p = 0; p < 4; p++){
        unsigned b0,b1,b2,b3;
        ldsm4(b0,b1,b2,b3, &sm.vT[p*16 + arow][k0 + acol]);
        mma16816(tmp[2*p],   a0,a1,a2,a3, b0,b2);
        mma16816(tmp[2*p+1], a0,a1,a2,a3, b1,b3);
      }
    }
    #pragma unroll
    for(int i=0;i<8;i++)
      #pragma unroll
      for(int j=0;j<4;j++) kvacc[i][j] = kvacc[i][j]*fo + tmp[i][j]*fn;
  }

  size_t pb = ((size_t)g*8 + split)*(MF*ED);
  int m0 = w*16+gg, m1 = m0+8;
  #pragma unroll
  for (int nt = 0; nt < 8; nt++){
    int e0 = nt*8 + 2*t;
    *(float2*)&g_kvp[pb + (size_t)m0*64 + e0] = make_float2(kvacc[nt][0], kvacc[nt][1]);
    *(float2*)&g_kvp[pb + (size_t)m1*64 + e0] = make_float2(kvacc[nt][2], kvacc[nt][3]);
  }
  sm.ks2[tid] = kpriv;
  __syncthreads();
  if (tid < 128) g_ksump[((size_t)g*8 + split)*MF + tid] = sm.ks2[tid];
  if (tid == 0) g_pstab[g*8 + split] = runstab;
}

// ======== K2: stab ; K3: merged kv+ksum reduction ========
__global__ void k_stab(){
  int g = blockIdx.x, lane = threadIdx.x;
  float v = g_tstab[g*32 + lane];
  #pragma unroll
  for (int o=16;o>0;o>>=1) v = fmaxf(v, __shfl_xor_sync(0xffffffffu,v,o));
  if (lane==0) g_stabk[g] = v;
}
__global__ void k_red(){
  int i = blockIdx.x*blockDim.x + threadIdx.x;
  if (i < NG*MF*ED){
    int g = i>>13, me = i&8191;
    float stabg = g_stabk[g], s = 0.f;
    #pragma unroll
    for (int p=0;p<8;p++)
      s += g_kvp[((size_t)g*8+p)*(MF*ED)+me] * __expf(g_pstab[g*8+p]-stabg);
    g_kv[i] = s;
  } else {
    int j = i - NG*MF*ED;
    if (j < NG*MF){
      int g = j>>7, m = j&127;
      float stabg = g_stabk[g], s = 0.f;
      #pragma unroll
      for (int p=0;p<8;p++)
        s += g_ksump[(size_t)(g*8+p)*MF+m] * __expf(g_pstab[g*8+p]-stabg);
      g_ksum[j] = s;
    }
  }
}

// ======== K4: phi_q (mma), pls, lr_v (mma), lr_1 ========
struct SQ {
  __half Bp[128][136];
  union { __half Aq[128][136]; __half phiA[128][136]; } u;   // phiA row-major [q][m]
  __half kvTh[64][136];
  __half kvTl[64][136];
  float snorm[128];
  float ksum[128];
};

__global__ void __launch_bounds__(256,2)
k_phiq(const float* __restrict__ query, const float* __restrict__ proj){
  extern __shared__ char raw[];
  SQ& sm = *reinterpret_cast<SQ*>(raw);
  int g = blockIdx.y;
  int c = g>>5, b = (g>>3)&3, h = g&7;
  int q0 = blockIdx.x*128;
  int tid = threadIdx.x, lane = tid&31, w = tid>>5;
  int gg = lane>>2, t = lane&3;
  int arow = (lane&7) + ((lane>>3)&1)*8, acol = (lane>>4)*8;

  for (int idx = tid; idx < 128*64; idx += 256){
    int m = idx>>6, e = idx&63;
    float x = proj[((size_t)c*MF+m)*ED+e];
    __half hh,ll; split16(x,hh,ll);
    sm.Bp[m][e]=hh; sm.Bp[m][64+e]=ll;
  }
  for (int idx = tid; idx < 128*64; idx += 256){
    int i = idx>>6, e = idx&63;
    float x = query[(((size_t)b*TT + (c*CHQ+q0+i))*NHk + h)*ED + e];
    __half hh,ll; split16(x,hh,ll);
    sm.u.Aq[i][e]=hh; sm.u.Aq[i][64+e]=ll;
  }
  for (int idx = tid; idx < 128*64; idx += 256){
    int m = idx>>6, e = idx&63;
    float x = g_kv[(size_t)g*MF*ED + m*64 + e];
    __half hh,ll; split16(x,hh,ll);
    sm.kvTh[e][m]=hh; sm.kvTl[e][m]=ll;
  }
  if (tid < 128) sm.ksum[tid] = g_ksum[g*MF+tid];
  __syncthreads();
  if (tid < 128){
    float s = 0.f;
    #pragma unroll
    for (int e = 0; e < 64; e++){
      float x = __half2float(sm.u.Aq[tid][e]) + __half2float(sm.u.Aq[tid][64+e]);
      s += x*x;
    }
    sm.snorm[tid] = 0.5f*s;
  }
  __syncthreads();

  int r0 = w*16+gg, r1 = r0+8;
  float fr[16][4];
  #pragma unroll
  for(int i=0;i<16;i++)
    #pragma unroll
    for(int j=0;j<4;j++) fr[i][j]=0.f;
  #pragma unroll
  for (int term = 0; term < 3; term++){
    int ao = c_ao[term], bo = c_bo[term];
    #pragma unroll
    for (int ks = 0; ks < 4; ks++){
      int k0 = ks*16;
      unsigned a0,a1,a2,a3;
      ldsm4(a0,a1,a2,a3, &sm.u.Aq[w*16 + arow][ao + k0 + acol]);
      #pragma unroll
      for (int p = 0; p < 8; p++){
        unsigned b0,b1,b2,b3;
        ldsm4(b0,b1,b2,b3, &sm.Bp[p*16 + arow][bo + k0 + acol]);
        mma16816(fr[2*p],   a0,a1,a2,a3, b0,b2);
        mma16816(fr[2*p+1], a0,a1,a2,a3, b1,b3);
      }
    }
  }
  float n0v = sm.snorm[r0], n1v = sm.snorm[r1];
  float m0 = -CUDART_INF_F, m1 = -CUDART_INF_F;
  #pragma unroll
  for(int ft=0;ft<16;ft++){
    fr[ft][0]-=n0v; fr[ft][1]-=n0v; fr[ft][2]-=n1v; fr[ft][3]-=n1v;
    m0 = fmaxf(m0, fmaxf(fr[ft][0], fr[ft][1]));
    m1 = fmaxf(m1, fmaxf(fr[ft][2], fr[ft][3]));
  }
  #pragma unroll
  for (int o=1;o<=2;o<<=1){
    m0 = fmaxf(m0, __shfl_xor_sync(0xffffffffu,m0,o));
    m1 = fmaxf(m1, __shfl_xor_sync(0xffffffffu,m1,o));
  }
  float skv = g_stabk[g];
  if (t == 0){
    g_pls[(size_t)g*CHQ + q0 + r0] = m0 + skv - LOGM;
    g_pls[(size_t)g*CHQ + q0 + r1] = m1 + skv - LOGM;
  }
  __syncthreads();
  size_t gq0 = ((size_t)g*CHQ+q0+r0)*MF;
  size_t gq1 = ((size_t)g*CHQ+q0+r1)*MF;
  #pragma unroll
  for(int ft=0;ft<16;ft++){
    int col = ft*8 + 2*t;
    __half h0 = __float2half_rn(__expf(fr[ft][0]-m0));
    __half h1 = __float2half_rn(__expf(fr[ft][1]-m0));
    __half h2 = __float2half_rn(__expf(fr[ft][2]-m1));
    __half h3 = __float2half_rn(__expf(fr[ft][3]-m1));
    __half2 p01 = __halves2half2(h0,h1), p23 = __halves2half2(h2,h3);
    *(__half2*)&sm.u.phiA[r0][col] = p01;
    *(__half2*)&sm.u.phiA[r1][col] = p23;
    *(__half2*)&g_phiqh[gq0+col] = p01;
    *(__half2*)&g_phiqh[gq1+col] = p23;
  }
  __syncthreads();

  float acc[8][4];
  #pragma unroll
  for(int i=0;i<8;i++)
    #pragma unroll
    for(int j=0;j<4;j++) acc[i][j]=0.f;
  #pragma unroll
  for (int pass=0; pass<2; pass++){
    #pragma unroll
    for (int ks = 0; ks < 8; ks++){
      int k0 = ks*16;
      unsigned a0,a1,a2,a3;
      ldsm4(a0,a1,a2,a3, &sm.u.phiA[w*16 + arow][k0 + acol]);
      #pragma unroll
      for (int p = 0; p < 4; p++){
        const __half* br = pass ? &sm.kvTl[p*16 + arow][k0 + acol]
                                : &sm.kvTh[p*16 + arow][k0 + acol];
        unsigned b0,b1,b2,b3;
        ldsm4(b0,b1,b2,b3, br);
        mma16816(acc[2*p],   a0,a1,a2,a3, b0,b2);
        mma16816(acc[2*p+1], a0,a1,a2,a3, b1,b3);
      }
    }
  }
  size_t ro0 = ((size_t)g*CHQ + q0 + r0)*ED;
  size_t ro1 = ((size_t)g*CHQ + q0 + r1)*ED;
  #pragma unroll
  for (int nt = 0; nt < 8; nt++){
    int e0 = nt*8 + 2*t;
    *(float2*)&g_lrv[ro0 + e0] = make_float2(acc[nt][0], acc[nt][1]);
    *(float2*)&g_lrv[ro1 + e0] = make_float2(acc[nt][2], acc[nt][3]);
  }
  if (tid < 128){
    const __half2* p2 = (const __half2*)&sm.u.phiA[tid][0];
    float s = 0.f;
    #pragma unroll
    for (int i = 0; i < 64; i++){
      float2 f = __half22float2(p2[i]);
      s += f.x*sm.ksum[2*i] + f.y*sm.ksum[2*i+1];
    }
    g_lr1[(size_t)g*CHQ + q0 + tid] = s;
  }
}

// ======== K5: local windows via mma (ldmatrix) ========
struct S5 {
  union { __half A_s[32][200]; __half cA[32][200]; } u;
  __half B_s[64][200];
  __half vT[64][200];
  __half pqA[32][136];
  __half pkB[64][136];
  float sc[32][66];
  float dp[32][66];
  float jscale[64];
  float lnorm[32];
  float scl[32];
};

__global__ void __launch_bounds__(256,2)
k_local(const float* __restrict__ query, const float* __restrict__ key,
        const float* __restrict__ value, float* __restrict__ out){
  extern __shared__ char raw[];
  S5& sm = *reinterpret_cast<S5*>(raw);
  int g = blockIdx.y, n = blockIdx.x;
  int c = g>>5, b = (g>>3)&3, h = g&7;
  int tid = threadIdx.x, lane = tid&31, w = tid>>5;
  int t = lane&3;
  int arow = (lane&7) + ((lane>>3)&1)*8, acol = (lane>>4)*8;
  int t0 = n*32, p0 = t0 - 16;
  float stabg = g_stabk[g];

  if (tid < 64){
    int pos = p0 + tid;
    sm.jscale[tid] = (pos >= 0) ? __expf(g_tstab[g*32 + (pos>>7)] - stabg) : 0.f;
  }
  for (int idx = tid; idx < 32*64; idx += 256){
    int qi = idx>>6, e = idx&63;
    float x = query[(((size_t)b*TT + (c*CHQ+t0+qi))*NHk + h)*ED + e];
    __half hh,ll; split16(x,hh,ll);
    sm.u.A_s[qi][e]=hh; sm.u.A_s[qi][64+e]=ll; sm.u.A_s[qi][128+e]=hh;
  }
  for (int idx = tid; idx < 64*64; idx += 256){
    int j = idx>>6, e = idx&63;
    int pos = p0 + j;
    float kx = 0.f, vx = 0.f;
    if (pos >= 0){
      size_t base = (((size_t)b*SEQ + pos)*NHk + h)*ED + e;
      kx = key[base]; vx = value[base];
    }
    __half hh,ll; split16(kx,hh,ll);
    sm.B_s[j][e]=hh; sm.B_s[j][64+e]=hh; sm.B_s[j][128+e]=ll;
    __half vh,vl; split16(vx,vh,vl);
    sm.vT[e][j]=vh; sm.vT[e][64+j]=vl; sm.vT[e][128+j]=vh;
  }
  for (int idx = tid; idx < 32*64; idx += 256){
    int qi = idx>>6, mp = idx&63;
    *(unsigned*)&sm.pqA[qi][2*mp] =
      *(const unsigned*)&g_phiqh[((size_t)g*CHQ + t0 + qi)*MF + 2*mp];
  }
  for (int idx = tid; idx < 64*64; idx += 256){
    int j = idx>>6, mp = idx&63;
    int pos = p0 + j;
    unsigned v = 0u;
    if (pos >= 0) v = *(const unsigned*)&g_phikh[((size_t)g*SEQ + pos)*MF + 2*mp];
    *(unsigned*)&sm.pkB[j][2*mp] = v;
  }
  __syncthreads();

  int mt = w&1, ntb = (w>>1)*2;
  int row0 = mt*16 + (lane>>2), row1 = row0+8;

  float cs[2][4], cd[2][4];
  #pragma unroll
  for(int i=0;i<2;i++)
    #pragma unroll
    for(int j=0;j<4;j++){ cs[i][j]=0.f; cd[i][j]=0.f; }
  #pragma unroll
  for (int ks = 0; ks < 12; ks++){
    int k0 = ks*16;
    unsigned a0,a1,a2,a3, b0,b1,b2,b3;
    ldsm4(a0,a1,a2,a3, &sm.u.A_s[mt*16 + arow][k0 + acol]);
    ldsm4(b0,b1,b2,b3, &sm.B_s[(w>>1)*16 + arow][k0 + acol]);
    mma16816(cs[0], a0,a1,a2,a3, b0,b2);
    mma16816(cs[1], a0,a1,a2,a3, b1,b3);
  }
  #pragma unroll
  for (int ks = 0; ks < 8; ks++){
    int k0 = ks*16;
    unsigned a0,a1,a2,a3, b0,b1,b2,b3;
    ldsm4(a0,a1,a2,a3, &sm.pqA[mt*16 + arow][k0 + acol]);
    ldsm4(b0,b1,b2,b3, &sm.pkB[(w>>1)*16 + arow][k0 + acol]);
    mma16816(cd[0], a0,a1,a2,a3, b0,b2);
    mma16816(cd[1], a0,a1,a2,a3, b1,b3);
  }
  #pragma unroll
  for (int ii = 0; ii < 2; ii++){
    int colb = (ntb+ii)*8 + 2*t;
    #pragma unroll
    for (int cc = 0; cc < 2; cc++){
      int j = colb + cc;
      float js = sm.jscale[j];
      bool ok = (p0 + j >= 0);
      bool v0 = ok && (j>=row0) && (j<row0+32);
      bool v1 = ok && (j>=row1) && (j<row1+32);
      cs[ii][cc]   = v0 ? cs[ii][cc]      : -1e24f;
      cs[ii][2+cc] = v1 ? cs[ii][2+cc]    : -1e24f;
      cd[ii][cc]   = v0 ? cd[ii][cc]*js   : 0.f;
      cd[ii][2+cc] = v1 ? cd[ii][2+cc]*js : 0.f;
      sm.sc[row0][j] = cs[ii][cc];
      sm.sc[row1][j] = cs[ii][2+cc];
      sm.dp[row0][j] = cd[ii][cc];
      sm.dp[row1][j] = cd[ii][2+cc];
    }
  }
  __syncthreads();

  #pragma unroll
  for(int r=0;r<4;r++){
    int row = w*4+r;
    float v0 = sm.sc[row][lane], v1 = sm.sc[row][lane+32];
    float mx = fmaxf(v0,v1);
    #pragma unroll
    for(int o=16;o>0;o>>=1) mx = fmaxf(mx, __shfl_xor_sync(0xffffffffu,mx,o));
    float se = __expf(v0-mx) + __expf(v1-mx);
    #pragma unroll
    for(int o=16;o>0;o>>=1) se += __shfl_xor_sync(0xffffffffu,se,o);
    float lse = mx + __logf(se);
    float ds = sm.dp[row][lane] + sm.dp[row][lane+32];
    #pragma unroll
    for(int o=16;o>0;o>>=1) ds += __shfl_xor_sync(0xffffffffu,ds,o);
    float lr1v = g_lr1[(size_t)g*CHQ + t0 + row];
    float plsv = g_pls[(size_t)g*CHQ + t0 + row];
    float rem = fmaxf(lr1v - ds, 1e-24f);
    float bq = __logf(rem) + plsv;
    float hi = fmaxf(lse,bq), lo2 = fminf(lse,bq);
    float ln = hi + __logf(1.f + __expf(lo2-hi));
    if (lane==0){ sm.lnorm[row]=ln; sm.scl[row]=__expf(plsv-ln); }
  }
  __syncthreads();

  float ln0 = sm.lnorm[row0], ln1 = sm.lnorm[row1];
  float s0v = sm.scl[row0], s1v = sm.scl[row1];
  #pragma unroll
  for (int ii = 0; ii < 2; ii++){
    int colb = (ntb+ii)*8 + 2*t;
    #pragma unroll
    for (int cc = 0; cc < 2; cc++){
      int j = colb + cc;
      float c0 = __expf(cs[ii][cc]   - ln0) - s0v*cd[ii][cc];
      float c1 = __expf(cs[ii][2+cc] - ln1) - s1v*cd[ii][2+cc];
      __half ch, cl;
      split16(c0, ch, cl);
      sm.u.cA[row0][j]=ch; sm.u.cA[row0][64+j]=ch; sm.u.cA[row0][128+j]=cl;
      split16(c1, ch, cl);
      sm.u.cA[row1][j]=ch; sm.u.cA[row1][64+j]=ch; sm.u.cA[row1][128+j]=cl;
    }
  }
  __syncthreads();

  float ep[2][4];
  #pragma unroll
  for(int i=0;i<2;i++)
    #pragma unroll
    for(int j=0;j<4;j++) ep[i][j]=0.f;
  #pragma unroll
  for (int ks = 0; ks < 12; ks++){
    int k0 = ks*16;
    unsigned a0,a1,a2,a3, b0,b1,b2,b3;
    ldsm4(a0,a1,a2,a3, &sm.u.cA[mt*16 + arow][k0 + acol]);
    ldsm4(b0,b1,b2,b3, &sm.vT[(w>>1)*16 + arow][k0 + acol]);
    mma16816(ep[0], a0,a1,a2,a3, b0,b2);
    mma16816(ep[1], a0,a1,a2,a3, b1,b3);
  }
  float sc0 = sm.scl[row0], sc1 = sm.scl[row1];
  size_t lr0 = ((size_t)g*CHQ + t0 + row0)*ED;
  size_t lr1o = ((size_t)g*CHQ + t0 + row1)*ED;
  size_t ob0 = (((size_t)b*NHk + h)*TT + (c*CHQ + t0 + row0))*ED;
  size_t ob1 = (((size_t)b*NHk + h)*TT + (c*CHQ + t0 + row1))*ED;
  #pragma unroll
  for (int ii = 0; ii < 2; ii++){
    int e0 = (ntb+ii)*8 + 2*t;
    float2 l0 = *(const float2*)&g_lrv[lr0 + e0];
    float2 l1 = *(const float2*)&g_lrv[lr1o + e0];
    out[ob0 + e0]   = ep[ii][0] + sc0*l0.x;
    out[ob0 + e0+1] = ep[ii][1] + sc0*l0.y;
    out[ob1 + e0]   = ep[ii][2] + sc1*l1.x;
    out[ob1 + e0+1] = ep[ii][3] + sc1*l1.y;
  }
}

// ---------------- launch ----------------
extern "C" void kernel_launch(void* const* d_in, const int* in_sizes, int n_in,
                              void* d_out, int out_size){
  const float* query = (const float*)d_in[0];
  const float* key   = (const float*)d_in[1];
  const float* value = (const float*)d_in[2];
  const float* proj  = (const float*)d_in[3];
  float* out = (float*)d_out;

  cudaFuncSetAttribute(k_phik, cudaFuncAttributeMaxDynamicSharedMemorySize, (int)sizeof(SP));
  cudaFuncSetAttribute(k_phiq, cudaFuncAttributeMaxDynamicSharedMemorySize, (int)sizeof(SQ));
  cudaFuncSetAttribute(k_local,cudaFuncAttributeMaxDynamicSharedMemorySize, (int)sizeof(S5));

  dim3 gp(8, NG);
  k_phik<<<gp, 256, sizeof(SP)>>>(key, value, proj);
  k_stab<<<NG, 32>>>();
  k_red<<<(NG*MF*ED + NG*MF + 255)/256, 256>>>();
  dim3 gq(CHQ/128, NG);
  k_phiq<<<gq, 256, sizeof(SQ)>>>(query, proj);
  dim3 g5(32, NG);
  k_local<<<g5, 256, sizeof(S5)>>>(query, key, value, out);
}